// round 4
// baseline (speedup 1.0000x reference)
#include <cuda_runtime.h>
#include <cuda_bf16.h>
#include <stdint.h>

// Problem shape (LlamaMorExpertRouter_30477087933212)
#define B 4
#define S 4096
#define H 2048
#define K 2048
#define ALPHA 0.1f

// Output layout in d_out (float32): out[B*K*H] | sel[B*K] | targets[B*S]
#define SEL_OFF   ((size_t)B * K * H)
#define TGT_OFF   (SEL_OFF + (size_t)B * K)

// Scratch (no device allocs allowed)
__device__ float g_probs[B * S];
__device__ int   g_sel[B * K];

// ---------------------------------------------------------------------------
// Kernel 1: router projection + sigmoid*alpha. One warp per token.
// 4 stages x 4 float4 loads with 4 accumulators -> deep MLP. HBM-bound.
// ---------------------------------------------------------------------------
__global__ __launch_bounds__(256) void router_kernel(
    const float* __restrict__ x, const float* __restrict__ w)
{
    int warp = (blockIdx.x * blockDim.x + threadIdx.x) >> 5;
    int lane = threadIdx.x & 31;
    if (warp >= B * S) return;

    const float4* xr = reinterpret_cast<const float4*>(x + (size_t)warp * H);
    const float4* wr = reinterpret_cast<const float4*>(w);

    float acc0 = 0.f, acc1 = 0.f, acc2 = 0.f, acc3 = 0.f;
#pragma unroll
    for (int i = 0; i < 4; i++) {            // 4 stages
        float4 a0 = xr[lane + 128 * i +  0];
        float4 a1 = xr[lane + 128 * i + 32];
        float4 a2 = xr[lane + 128 * i + 64];
        float4 a3 = xr[lane + 128 * i + 96];
        float4 b0 = wr[lane + 128 * i +  0];
        float4 b1 = wr[lane + 128 * i + 32];
        float4 b2 = wr[lane + 128 * i + 64];
        float4 b3 = wr[lane + 128 * i + 96];
        acc0 += a0.x * b0.x + a0.y * b0.y + a0.z * b0.z + a0.w * b0.w;
        acc1 += a1.x * b1.x + a1.y * b1.y + a1.z * b1.z + a1.w * b1.w;
        acc2 += a2.x * b2.x + a2.y * b2.y + a2.z * b2.z + a2.w * b2.w;
        acc3 += a3.x * b3.x + a3.y * b3.y + a3.z * b3.z + a3.w * b3.w;
    }
    float acc = (acc0 + acc1) + (acc2 + acc3);
#pragma unroll
    for (int o = 16; o; o >>= 1)
        acc += __shfl_xor_sync(0xFFFFFFFFu, acc, o);

    if (lane == 0)
        g_probs[warp] = ALPHA / (1.0f + expf(-acc));   // sigmoid * alpha
}

// ---------------------------------------------------------------------------
// Block-wide exclusive scan (1024 threads) via warp shuffles.
// ---------------------------------------------------------------------------
__device__ __forceinline__ int block_exscan(int v, int* wsum)
{
    int lane = threadIdx.x & 31;
    int wid  = threadIdx.x >> 5;

    __syncthreads();                 // protect wsum reuse across calls
    int inc = v;
#pragma unroll
    for (int o = 1; o < 32; o <<= 1) {
        int y = __shfl_up_sync(0xFFFFFFFFu, inc, o);
        if (lane >= o) inc += y;
    }
    if (lane == 31) wsum[wid] = inc;
    __syncthreads();
    if (wid == 0) {
        int s = wsum[lane];
#pragma unroll
        for (int o = 1; o < 32; o <<= 1) {
            int y = __shfl_up_sync(0xFFFFFFFFu, s, o);
            if (lane >= o) s += y;
        }
        wsum[lane] = s;
    }
    __syncthreads();
    int warp_excl = (wid == 0) ? 0 : wsum[wid - 1];
    return warp_excl + inc - v;
}

// ---------------------------------------------------------------------------
// Kernel 2: per-batch top-K via MSB radix select on float bits (positive
// probs => bit order == value order). Values in registers; histogram via
// warp-aggregated atomics; parallel suffix scan finds the threshold bucket.
// Ties at the threshold break toward smaller index (jax.lax.top_k order).
// One 1024-thread block per batch.
// ---------------------------------------------------------------------------
__global__ __launch_bounds__(1024) void select_kernel(
    float* __restrict__ out_sel, float* __restrict__ out_tgt)
{
    __shared__ int hist[256];
    __shared__ int wsum[32];
    __shared__ int sh_d, sh_cum;

    const int b = blockIdx.x;
    const int t = threadIdx.x;
    const int lane = t & 31;
    const int base = t * 4;

    float4 pv = reinterpret_cast<const float4*>(g_probs + b * S)[t];
    unsigned v0 = __float_as_uint(pv.x), v1 = __float_as_uint(pv.y);
    unsigned v2 = __float_as_uint(pv.z), v3 = __float_as_uint(pv.w);

    unsigned prefix = 0, prefmask = 0;
    int remaining = K;

#pragma unroll
    for (int pass = 0; pass < 4; pass++) {
        const int shift = 24 - 8 * pass;
        if (t < 256) hist[t] = 0;
        __syncthreads();

        unsigned vals[4] = {v0, v1, v2, v3};
#pragma unroll
        for (int q = 0; q < 4; q++) {
            unsigned v = vals[q];
            bool ok = ((v & prefmask) == prefix);
            unsigned key = ok ? ((v >> shift) & 255u) : 0x100u;
            unsigned peers = __match_any_sync(0xFFFFFFFFu, key);
            if (ok && lane == (__ffs(peers) - 1))
                atomicAdd(&hist[key], __popc(peers));
        }
        __syncthreads();

        // parallel suffix scan over 256 buckets: thread t owns bucket 255-t
        int hv = 0, incw = 0;
        if (t < 256) {
            hv = hist[255 - t];
            incw = hv;
#pragma unroll
            for (int o = 1; o < 32; o <<= 1) {
                int y = __shfl_up_sync(0xFFFFFFFFu, incw, o);
                if (lane >= o) incw += y;
            }
            if (lane == 31) wsum[t >> 5] = incw;
        }
        __syncthreads();
        if (t < 256) {
            int add = 0;
            int wid8 = t >> 5;
#pragma unroll
            for (int j = 0; j < 8; j++)
                if (j < wid8) add += wsum[j];
            int incl = incw + add;      // suffix sum down to this bucket
            int excl = incl - hv;       // sum of strictly higher buckets
            if (excl < remaining && remaining <= incl) {
                sh_d = 255 - t;
                sh_cum = excl;
            }
        }
        __syncthreads();
        remaining -= sh_cum;
        prefix |= ((unsigned)sh_d) << shift;
        prefmask |= 0xFFu << shift;
        __syncthreads();
    }

    const unsigned T = prefix;   // exact bits of K-th largest value
    const int R = remaining;     // ties (bits==T) to take, by smallest index

    int e0 = (v0 == T), e1 = (v1 == T), e2 = (v2 == T), e3 = (v3 == T);
    int eqpre = block_exscan(e0 + e1 + e2 + e3, wsum);

    int s0 = (v0 > T) || (e0 && (eqpre                 < R));
    int s1 = (v1 > T) || (e1 && (eqpre + e0            < R));
    int s2 = (v2 > T) || (e2 && (eqpre + e0 + e1       < R));
    int s3 = (v3 > T) || (e3 && (eqpre + e0 + e1 + e2  < R));

    int pos = block_exscan(s0 + s1 + s2 + s3, wsum);

    int*   selp = g_sel   + b * K;
    float* selo = out_sel + (size_t)b * K;
    float* tgto = out_tgt + (size_t)b * S;

    int sv[4] = {s0, s1, s2, s3};
#pragma unroll
    for (int q = 0; q < 4; q++) {
        int idx = base + q;
        tgto[idx] = sv[q] ? 1.0f : 0.0f;
        if (sv[q]) {
            selp[pos] = idx;
            selo[pos] = (float)idx;
            pos++;
        }
    }
}

// ---------------------------------------------------------------------------
// Kernel 3: gather selected tokens and scale. 512 threads = one 8KB row in a
// single load+store per thread. Streaming stores (__stcs) keep the output
// from evicting x (largely L2-resident right after the router pass).
// ---------------------------------------------------------------------------
__global__ __launch_bounds__(512) void gather_kernel(
    const float* __restrict__ x, float* __restrict__ out)
{
    int bj = blockIdx.x;                 // 0 .. B*K-1
    int b  = bj >> 11;                   // / K
    int idx = g_sel[bj];
    float wv = g_probs[b * S + idx];

    const float4* src = reinterpret_cast<const float4*>(
        x + ((size_t)b * S + (size_t)idx) * H);
    float4* dst = reinterpret_cast<float4*>(out + (size_t)bj * H);

    float4 v = __ldg(&src[threadIdx.x]);
    v.x *= wv; v.y *= wv; v.z *= wv; v.w *= wv;
    __stcs(&dst[threadIdx.x], v);
}

// ---------------------------------------------------------------------------
extern "C" void kernel_launch(void* const* d_in, const int* in_sizes, int n_in,
                              void* d_out, int out_size)
{
    const float* x = (const float*)d_in[0];        // [B,S,H] f32
    const float* w = (const float*)d_in[1];        // [1,H]   f32
    float* out = (float*)d_out;

    float* out_main = out;             // [B,K,H]
    float* out_sel  = out + SEL_OFF;   // [B,K]
    float* out_tgt  = out + TGT_OFF;   // [B,S]

    router_kernel<<<(B * S) / 8, 256>>>(x, w);
    select_kernel<<<B, 1024>>>(out_sel, out_tgt);
    gather_kernel<<<B * K, 512>>>(x, out_main);
}

// round 5
// speedup vs baseline: 1.0289x; 1.0289x over previous
#include <cuda_runtime.h>
#include <cuda_bf16.h>
#include <stdint.h>

// Problem shape (LlamaMorExpertRouter_30477087933212)
#define B 4
#define S 4096
#define H 2048
#define K 2048
#define ALPHA 0.1f

// Output layout in d_out (float32): out[B*K*H] | sel[B*K] | targets[B*S]
#define SEL_OFF   ((size_t)B * K * H)
#define TGT_OFF   (SEL_OFF + (size_t)B * K)

#define ROUTER_BLOCKS 1024    // 8192 warps, 2 tokens each -> single wave
#define GATHER_BLOCKS 1184    // 148 SMs * 8 blocks resident -> single wave

// Scratch (no device allocs allowed)
__device__ float g_probs[B * S];
__device__ int   g_sel[B * K];

// ---------------------------------------------------------------------------
// dot(x_row, w) over H=2048 with one warp; 4 stages x 4 independent loads.
// ---------------------------------------------------------------------------
__device__ __forceinline__ float warp_dot_row(
    const float4* __restrict__ xr, const float4* __restrict__ wr, int lane)
{
    float acc0 = 0.f, acc1 = 0.f, acc2 = 0.f, acc3 = 0.f;
#pragma unroll
    for (int i = 0; i < 4; i++) {
        float4 a0 = xr[lane + 128 * i +  0];
        float4 a1 = xr[lane + 128 * i + 32];
        float4 a2 = xr[lane + 128 * i + 64];
        float4 a3 = xr[lane + 128 * i + 96];
        float4 b0 = wr[lane + 128 * i +  0];
        float4 b1 = wr[lane + 128 * i + 32];
        float4 b2 = wr[lane + 128 * i + 64];
        float4 b3 = wr[lane + 128 * i + 96];
        acc0 += a0.x * b0.x + a0.y * b0.y + a0.z * b0.z + a0.w * b0.w;
        acc1 += a1.x * b1.x + a1.y * b1.y + a1.z * b1.z + a1.w * b1.w;
        acc2 += a2.x * b2.x + a2.y * b2.y + a2.z * b2.z + a2.w * b2.w;
        acc3 += a3.x * b3.x + a3.y * b3.y + a3.z * b3.z + a3.w * b3.w;
    }
    float acc = (acc0 + acc1) + (acc2 + acc3);
#pragma unroll
    for (int o = 16; o; o >>= 1)
        acc += __shfl_xor_sync(0xFFFFFFFFu, acc, o);
    return acc;
}

// ---------------------------------------------------------------------------
// Kernel 1: router projection + sigmoid*alpha. One warp per 2 tokens;
// grid sized for exactly one balanced wave. HBM-bound.
// ---------------------------------------------------------------------------
__global__ __launch_bounds__(256) void router_kernel(
    const float* __restrict__ x, const float* __restrict__ w)
{
    int gw   = (blockIdx.x * blockDim.x + threadIdx.x) >> 5;  // 0..8191
    int lane = threadIdx.x & 31;

    const float4* wr = reinterpret_cast<const float4*>(w);
    int t0 = gw * 2;

    const float4* xr0 = reinterpret_cast<const float4*>(x + (size_t)t0 * H);
    float d0 = warp_dot_row(xr0, wr, lane);
    const float4* xr1 = reinterpret_cast<const float4*>(x + (size_t)(t0 + 1) * H);
    float d1 = warp_dot_row(xr1, wr, lane);

    if (lane == 0) {
        g_probs[t0]     = ALPHA / (1.0f + expf(-d0));
        g_probs[t0 + 1] = ALPHA / (1.0f + expf(-d1));
    }
}

// ---------------------------------------------------------------------------
// Block-wide exclusive scan (1024 threads) via warp shuffles.
// ---------------------------------------------------------------------------
__device__ __forceinline__ int block_exscan(int v, int* wsum)
{
    int lane = threadIdx.x & 31;
    int wid  = threadIdx.x >> 5;

    __syncthreads();                 // protect wsum reuse across calls
    int inc = v;
#pragma unroll
    for (int o = 1; o < 32; o <<= 1) {
        int y = __shfl_up_sync(0xFFFFFFFFu, inc, o);
        if (lane >= o) inc += y;
    }
    if (lane == 31) wsum[wid] = inc;
    __syncthreads();
    if (wid == 0) {
        int s = wsum[lane];
#pragma unroll
        for (int o = 1; o < 32; o <<= 1) {
            int y = __shfl_up_sync(0xFFFFFFFFu, s, o);
            if (lane >= o) s += y;
        }
        wsum[lane] = s;
    }
    __syncthreads();
    int warp_excl = (wid == 0) ? 0 : wsum[wid - 1];
    return warp_excl + inc - v;
}

// ---------------------------------------------------------------------------
// Kernel 2: per-batch top-K via MSB radix select on float bits (positive
// probs => bit order == value order). Values in registers; histogram via
// warp-aggregated atomics; parallel suffix scan finds the threshold bucket.
// Ties break toward smaller index (jax.lax.top_k order). One block/batch.
// ---------------------------------------------------------------------------
__global__ __launch_bounds__(1024) void select_kernel(
    float* __restrict__ out_sel, float* __restrict__ out_tgt)
{
    __shared__ int hist[256];
    __shared__ int wsum[32];
    __shared__ int sh_d, sh_cum;

    const int b = blockIdx.x;
    const int t = threadIdx.x;
    const int lane = t & 31;
    const int base = t * 4;

    float4 pv = reinterpret_cast<const float4*>(g_probs + b * S)[t];
    unsigned v0 = __float_as_uint(pv.x), v1 = __float_as_uint(pv.y);
    unsigned v2 = __float_as_uint(pv.z), v3 = __float_as_uint(pv.w);

    unsigned prefix = 0, prefmask = 0;
    int remaining = K;

#pragma unroll
    for (int pass = 0; pass < 4; pass++) {
        const int shift = 24 - 8 * pass;
        if (t < 256) hist[t] = 0;
        __syncthreads();

        unsigned vals[4] = {v0, v1, v2, v3};
#pragma unroll
        for (int q = 0; q < 4; q++) {
            unsigned v = vals[q];
            bool ok = ((v & prefmask) == prefix);
            unsigned key = ok ? ((v >> shift) & 255u) : 0x100u;
            unsigned peers = __match_any_sync(0xFFFFFFFFu, key);
            if (ok && lane == (__ffs(peers) - 1))
                atomicAdd(&hist[key], __popc(peers));
        }
        __syncthreads();

        // parallel suffix scan over 256 buckets: thread t owns bucket 255-t
        int hv = 0, incw = 0;
        if (t < 256) {
            hv = hist[255 - t];
            incw = hv;
#pragma unroll
            for (int o = 1; o < 32; o <<= 1) {
                int y = __shfl_up_sync(0xFFFFFFFFu, incw, o);
                if (lane >= o) incw += y;
            }
            if (lane == 31) wsum[t >> 5] = incw;
        }
        __syncthreads();
        if (t < 256) {
            int add = 0;
            int wid8 = t >> 5;
#pragma unroll
            for (int j = 0; j < 8; j++)
                if (j < wid8) add += wsum[j];
            int incl = incw + add;      // suffix sum down to this bucket
            int excl = incl - hv;       // strictly higher buckets
            if (excl < remaining && remaining <= incl) {
                sh_d = 255 - t;
                sh_cum = excl;
            }
        }
        __syncthreads();
        remaining -= sh_cum;
        prefix |= ((unsigned)sh_d) << shift;
        prefmask |= 0xFFu << shift;
        __syncthreads();
    }

    const unsigned T = prefix;   // exact bits of K-th largest value
    const int R = remaining;     // ties (bits==T) to take, by smallest index

    int e0 = (v0 == T), e1 = (v1 == T), e2 = (v2 == T), e3 = (v3 == T);
    int eqpre = block_exscan(e0 + e1 + e2 + e3, wsum);

    int s0 = (v0 > T) || (e0 && (eqpre                 < R));
    int s1 = (v1 > T) || (e1 && (eqpre + e0            < R));
    int s2 = (v2 > T) || (e2 && (eqpre + e0 + e1       < R));
    int s3 = (v3 > T) || (e3 && (eqpre + e0 + e1 + e2  < R));

    int pos = block_exscan(s0 + s1 + s2 + s3, wsum);

    int*   selp = g_sel   + b * K;
    float* selo = out_sel + (size_t)b * K;
    float* tgto = out_tgt + (size_t)b * S;

    int sv[4] = {s0, s1, s2, s3};
#pragma unroll
    for (int q = 0; q < 4; q++) {
        int idx = base + q;
        tgto[idx] = sv[q] ? 1.0f : 0.0f;
        if (sv[q]) {
            selp[pos] = idx;
            selo[pos] = (float)idx;
            pos++;
        }
    }
}

// ---------------------------------------------------------------------------
// Kernel 3: gather selected tokens and scale. Persistent grid-stride over
// rows (single balanced wave); 2 independent float4 load/stores per thread
// per row (round-3 inner shape). __stcs keeps the output stream from
// evicting x (largely L2-resident after the router pass).
// ---------------------------------------------------------------------------
__global__ __launch_bounds__(256) void gather_kernel(
    const float* __restrict__ x, float* __restrict__ out)
{
    for (int bj = blockIdx.x; bj < B * K; bj += GATHER_BLOCKS) {
        int b   = bj >> 11;                  // / K
        int idx = g_sel[bj];
        float wv = g_probs[b * S + idx];

        const float4* src = reinterpret_cast<const float4*>(
            x + ((size_t)b * S + (size_t)idx) * H);
        float4* dst = reinterpret_cast<float4*>(out + (size_t)bj * H);

        float4 v0 = src[threadIdx.x];
        float4 v1 = src[threadIdx.x + 256];
        v0.x *= wv; v0.y *= wv; v0.z *= wv; v0.w *= wv;
        v1.x *= wv; v1.y *= wv; v1.z *= wv; v1.w *= wv;
        __stcs(&dst[threadIdx.x],       v0);
        __stcs(&dst[threadIdx.x + 256], v1);
    }
}

// ---------------------------------------------------------------------------
extern "C" void kernel_launch(void* const* d_in, const int* in_sizes, int n_in,
                              void* d_out, int out_size)
{
    const float* x = (const float*)d_in[0];        // [B,S,H] f32
    const float* w = (const float*)d_in[1];        // [1,H]   f32
    float* out = (float*)d_out;

    float* out_main = out;             // [B,K,H]
    float* out_sel  = out + SEL_OFF;   // [B,K]
    float* out_tgt  = out + TGT_OFF;   // [B,S]

    router_kernel<<<ROUTER_BLOCKS, 256>>>(x, w);
    select_kernel<<<B, 1024>>>(out_sel, out_tgt);
    gather_kernel<<<GATHER_BLOCKS, 256>>>(x, out_main);
}

// round 6
// speedup vs baseline: 1.1509x; 1.1185x over previous
#include <cuda_runtime.h>
#include <cuda_bf16.h>
#include <stdint.h>

// Problem shape (LlamaMorExpertRouter_30477087933212)
#define B 4
#define S 4096
#define H 2048
#define K 2048
#define ALPHA 0.1f

// Output layout in d_out (float32): out[B*K*H] | sel[B*K] | targets[B*S]
#define SEL_OFF   ((size_t)B * K * H)
#define TGT_OFF   (SEL_OFF + (size_t)B * K)

#define GATHER_BLOCKS 1184    // 148 SMs * 8 resident blocks -> one wave

// Scratch (no device allocs allowed)
__device__ float g_probs[B * S];
__device__ int   g_sel[B * K];

// ---------------------------------------------------------------------------
// Kernel 1: router projection + sigmoid*alpha. One warp per token (R3 shape,
// best measured: ~25us @ 5.5TB/s). Block->token map REVERSED so the router
// streams x descending: at kernel end L2 holds the HEAD of x, which the
// gather kernel then sweeps first (ascending) -> cross-kernel L2 reuse.
// ---------------------------------------------------------------------------
__global__ __launch_bounds__(256) void router_kernel(
    const float* __restrict__ x, const float* __restrict__ w)
{
    int warp = (blockIdx.x * blockDim.x + threadIdx.x) >> 5;
    int lane = threadIdx.x & 31;
    int tok  = (B * S - 1) - warp;          // reversed sweep

    const float4* xr = reinterpret_cast<const float4*>(x + (size_t)tok * H);
    const float4* wr = reinterpret_cast<const float4*>(w);

    float acc0 = 0.0f, acc1 = 0.0f;
#pragma unroll
    for (int i = 0; i < H / (4 * 64); i++) {   // 8 iters, 2 loads each
        float4 a0 = xr[lane + 64 * i];
        float4 b0 = wr[lane + 64 * i];
        float4 a1 = xr[lane + 32 + 64 * i];
        float4 b1 = wr[lane + 32 + 64 * i];
        acc0 += a0.x * b0.x + a0.y * b0.y + a0.z * b0.z + a0.w * b0.w;
        acc1 += a1.x * b1.x + a1.y * b1.y + a1.z * b1.z + a1.w * b1.w;
    }
    float acc = acc0 + acc1;
#pragma unroll
    for (int o = 16; o; o >>= 1)
        acc += __shfl_xor_sync(0xFFFFFFFFu, acc, o);

    if (lane == 0)
        g_probs[tok] = ALPHA / (1.0f + expf(-acc));   // sigmoid * alpha
}

// ---------------------------------------------------------------------------
// Block-wide exclusive scan (1024 threads) via warp shuffles.
// ---------------------------------------------------------------------------
__device__ __forceinline__ int block_exscan(int v, int* wsum)
{
    int lane = threadIdx.x & 31;
    int wid  = threadIdx.x >> 5;

    __syncthreads();                 // protect wsum reuse across calls
    int inc = v;
#pragma unroll
    for (int o = 1; o < 32; o <<= 1) {
        int y = __shfl_up_sync(0xFFFFFFFFu, inc, o);
        if (lane >= o) inc += y;
    }
    if (lane == 31) wsum[wid] = inc;
    __syncthreads();
    if (wid == 0) {
        int s = wsum[lane];
#pragma unroll
        for (int o = 1; o < 32; o <<= 1) {
            int y = __shfl_up_sync(0xFFFFFFFFu, s, o);
            if (lane >= o) s += y;
        }
        wsum[lane] = s;
    }
    __syncthreads();
    int warp_excl = (wid == 0) ? 0 : wsum[wid - 1];
    return warp_excl + inc - v;
}

// ---------------------------------------------------------------------------
// Kernel 2: per-batch top-K via MSB radix select on float bits (positive
// probs => bit order == value order). Values in registers; histogram via
// warp-aggregated atomics; parallel suffix scan finds the threshold bucket.
// Ties break toward smaller index (jax.lax.top_k order). One block/batch.
// ---------------------------------------------------------------------------
__global__ __launch_bounds__(1024) void select_kernel(
    float* __restrict__ out_sel, float* __restrict__ out_tgt)
{
    __shared__ int hist[256];
    __shared__ int wsum[32];
    __shared__ int sh_d, sh_cum;

    const int b = blockIdx.x;
    const int t = threadIdx.x;
    const int lane = t & 31;
    const int base = t * 4;

    float4 pv = reinterpret_cast<const float4*>(g_probs + b * S)[t];
    unsigned v0 = __float_as_uint(pv.x), v1 = __float_as_uint(pv.y);
    unsigned v2 = __float_as_uint(pv.z), v3 = __float_as_uint(pv.w);

    unsigned prefix = 0, prefmask = 0;
    int remaining = K;

#pragma unroll
    for (int pass = 0; pass < 4; pass++) {
        const int shift = 24 - 8 * pass;
        if (t < 256) hist[t] = 0;
        __syncthreads();

        unsigned vals[4] = {v0, v1, v2, v3};
#pragma unroll
        for (int q = 0; q < 4; q++) {
            unsigned v = vals[q];
            bool ok = ((v & prefmask) == prefix);
            unsigned key = ok ? ((v >> shift) & 255u) : 0x100u;
            unsigned peers = __match_any_sync(0xFFFFFFFFu, key);
            if (ok && lane == (__ffs(peers) - 1))
                atomicAdd(&hist[key], __popc(peers));
        }
        __syncthreads();

        // parallel suffix scan over 256 buckets: thread t owns bucket 255-t
        int hv = 0, incw = 0;
        if (t < 256) {
            hv = hist[255 - t];
            incw = hv;
#pragma unroll
            for (int o = 1; o < 32; o <<= 1) {
                int y = __shfl_up_sync(0xFFFFFFFFu, incw, o);
                if (lane >= o) incw += y;
            }
            if (lane == 31) wsum[t >> 5] = incw;
        }
        __syncthreads();
        if (t < 256) {
            int add = 0;
            int wid8 = t >> 5;
#pragma unroll
            for (int j = 0; j < 8; j++)
                if (j < wid8) add += wsum[j];
            int incl = incw + add;      // suffix sum down to this bucket
            int excl = incl - hv;       // strictly higher buckets
            if (excl < remaining && remaining <= incl) {
                sh_d = 255 - t;
                sh_cum = excl;
            }
        }
        __syncthreads();
        remaining -= sh_cum;
        prefix |= ((unsigned)sh_d) << shift;
        prefmask |= 0xFFu << shift;
        __syncthreads();
    }

    const unsigned T = prefix;   // exact bits of K-th largest value
    const int R = remaining;     // ties (bits==T) to take, by smallest index

    int e0 = (v0 == T), e1 = (v1 == T), e2 = (v2 == T), e3 = (v3 == T);
    int eqpre = block_exscan(e0 + e1 + e2 + e3, wsum);

    int s0 = (v0 > T) || (e0 && (eqpre                 < R));
    int s1 = (v1 > T) || (e1 && (eqpre + e0            < R));
    int s2 = (v2 > T) || (e2 && (eqpre + e0 + e1       < R));
    int s3 = (v3 > T) || (e3 && (eqpre + e0 + e1 + e2  < R));

    int pos = block_exscan(s0 + s1 + s2 + s3, wsum);

    int*   selp = g_sel   + b * K;
    float* selo = out_sel + (size_t)b * K;
    float* tgto = out_tgt + (size_t)b * S;

    int sv[4] = {s0, s1, s2, s3};
#pragma unroll
    for (int q = 0; q < 4; q++) {
        int idx = base + q;
        tgto[idx] = sv[q] ? 1.0f : 0.0f;
        if (sv[q]) {
            selp[pos] = idx;
            selo[pos] = (float)idx;
            pos++;
        }
    }
}

// ---------------------------------------------------------------------------
// Kernel 3: gather selected tokens and scale. Persistent grid-stride over
// rows, ascending sweep (meets the router's descending sweep at the head of
// x for L2 reuse); 2 independent float4 load/stores per thread per row.
// __stcs keeps the output stream from evicting x.
// ---------------------------------------------------------------------------
__global__ __launch_bounds__(256) void gather_kernel(
    const float* __restrict__ x, float* __restrict__ out)
{
    for (int bj = blockIdx.x; bj < B * K; bj += GATHER_BLOCKS) {
        int b   = bj >> 11;                  // / K
        int idx = g_sel[bj];
        float wv = g_probs[b * S + idx];

        const float4* src = reinterpret_cast<const float4*>(
            x + ((size_t)b * S + (size_t)idx) * H);
        float4* dst = reinterpret_cast<float4*>(out + (size_t)bj * H);

        float4 v0 = src[threadIdx.x];
        float4 v1 = src[threadIdx.x + 256];
        v0.x *= wv; v0.y *= wv; v0.z *= wv; v0.w *= wv;
        v1.x *= wv; v1.y *= wv; v1.z *= wv; v1.w *= wv;
        __stcs(&dst[threadIdx.x],       v0);
        __stcs(&dst[threadIdx.x + 256], v1);
    }
}

// ---------------------------------------------------------------------------
extern "C" void kernel_launch(void* const* d_in, const int* in_sizes, int n_in,
                              void* d_out, int out_size)
{
    const float* x = (const float*)d_in[0];        // [B,S,H] f32
    const float* w = (const float*)d_in[1];        // [1,H]   f32
    float* out = (float*)d_out;

    float* out_main = out;             // [B,K,H]
    float* out_sel  = out + SEL_OFF;   // [B,K]
    float* out_tgt  = out + TGT_OFF;   // [B,S]

    router_kernel<<<(B * S) / 8, 256>>>(x, w);
    select_kernel<<<B, 1024>>>(out_sel, out_tgt);
    gather_kernel<<<GATHER_BLOCKS, 256>>>(x, out_main);
}